// round 7
// baseline (speedup 1.0000x reference)
#include <cuda_runtime.h>
#include <cstdint>

// Problem constants
#define BB    8192
#define TT    100
#define TGTN  60

#define NT    512     // threads per CTA (16 warps)
#define BR    32      // batch rows per CTA
#define HPAD  36      // state row stride (floats)
#define LDK   9       // weight ring row stride (8 data + 1 pad) -> conflict-free
#define CHUNKF (512*LDK)   // 4608 floats per ring buffer

// Shared layout (float offsets)
#define OFF_H0   0
#define OFF_H1   4608               // 128*36
#define OFF_WBUF 9216               // 3 ring buffers x 4608
#define OFF_XS   23040              // [16][36]
#define OFF_FC   23616              // fcW [2][128]
#define OFF_FCB  23872              // fcb [2] (+2 pad)
#define OFF_BIAS 23876              // 4 sets x 512 combined biases
#define OFF_DW   25924              // dWih0 native [512][2]
#define SMEM_FLOATS 26948
#define SMEM_BYTES  (SMEM_FLOATS*4) // 107,792 B -> 2 CTAs/SM

typedef unsigned long long u64;

// ---- packed f32x2 helpers ----
__device__ __forceinline__ u64 pk2(float x) {
    u64 r; asm("mov.b64 %0, {%1, %1};" : "=l"(r) : "f"(x)); return r;
}
__device__ __forceinline__ u64 f2fma(u64 a, u64 b, u64 c) {
    u64 d; asm("fma.rn.f32x2 %0, %1, %2, %3;" : "=l"(d) : "l"(a), "l"(b), "l"(c)); return d;
}
__device__ __forceinline__ float2 up2(u64 v) {
    float2 f; asm("mov.b64 {%0, %1}, %2;" : "=f"(f.x), "=f"(f.y) : "l"(v)); return f;
}

// ---- activations ----
__device__ __forceinline__ float sigm(float x) {
    return __fdividef(1.0f, 1.0f + __expf(-x));
}
__device__ __forceinline__ float tanh_(float x) {
    float a = fabsf(x);
    float e = __expf(-2.0f * a);
    float t = __fdividef(1.0f - e, 1.0f + e);
    return copysignf(t, x);
}

__device__ __forceinline__ void init_acc(u64 acc[4][4], const float* __restrict__ bias, int j)
{
#pragma unroll
    for (int g = 0; g < 4; g++) {
        u64 b = pk2(bias[g * 128 + j]);
#pragma unroll
        for (int p = 0; p < 4; p++) acc[g][p] = b;
    }
}

// ---- streamed GEMM over K = NCH*8: cp.async 3-buffer ring, depth-2 prefetch,
//      ONE barrier per chunk. W is [512][ldw] row-major in global. ----
template<int NCH>
__device__ __forceinline__ void gemm_cp(u64 acc[4][4],
                                        const float* __restrict__ W, int ldw,
                                        const float* __restrict__ hb,
                                        const float* __restrict__ sm,
                                        uint32_t smem_u32, int tid, int j)
{
    auto issue = [&](int c) {
        uint32_t dst = smem_u32 + (uint32_t)((OFF_WBUF + (c % 3) * CHUNKF + tid * LDK) * 4);
        const float* src = W + (size_t)tid * ldw + c * 8;
#pragma unroll
        for (int q = 0; q < 8; q++)
            asm volatile("cp.async.ca.shared.global [%0], [%1], 4;"
                         :: "r"(dst + 4u * q), "l"(src + q));
        asm volatile("cp.async.commit_group;" ::: "memory");
    };
    issue(0);
    if (NCH > 1) issue(1);
#pragma unroll 1
    for (int c = 0; c < NCH; c++) {
        if (c + 1 < NCH) asm volatile("cp.async.wait_group 1;" ::: "memory");
        else             asm volatile("cp.async.wait_group 0;" ::: "memory");
        __syncthreads();                 // chunk c visible to all; buf[(c+2)%3] free
        if (c + 2 < NCH) issue(c + 2);
        const float* wb = sm + OFF_WBUF + (c % 3) * CHUNKF;
        const float* hc = hb + c * 8 * HPAD;
#pragma unroll
        for (int k = 0; k < 8; k++) {
            const float* w = wb + j * LDK + k;
            u64 b0 = pk2(w[0]);
            u64 b1 = pk2(w[128 * LDK]);
            u64 b2 = pk2(w[256 * LDK]);
            u64 b3 = pk2(w[384 * LDK]);
            const ulonglong2* hp = (const ulonglong2*)(hc + k * HPAD);
            ulonglong2 q0 = hp[0], q1 = hp[1];
            u64 a[4] = {q0.x, q0.y, q1.x, q1.y};
#pragma unroll
            for (int p = 0; p < 4; p++) {
                acc[0][p] = f2fma(a[p], b0, acc[0][p]);
                acc[1][p] = f2fma(a[p], b1, acc[1][p]);
                acc[2][p] = f2fma(a[p], b2, acc[2][p]);
                acc[3][p] = f2fma(a[p], b3, acc[3][p]);
            }
        }
    }
    __syncthreads();   // ring reusable by next call
}

// ---- LSTM pointwise epilogue: c-state in registers, h -> shared ----
__device__ __forceinline__ void epilogue(u64 acc[4][4],
                                         float2 cst[4],
                                         float* __restrict__ hs,
                                         int j, int rb)
{
    float2* hp = (float2*)(hs + j * HPAD + rb * 8);
#pragma unroll
    for (int p = 0; p < 4; p++) {
        float2 gi = up2(acc[0][p]);
        float2 gf = up2(acc[1][p]);
        float2 gg = up2(acc[2][p]);
        float2 go = up2(acc[3][p]);
        float2 c = cst[p];
        float cn0 = sigm(gf.x) * c.x + sigm(gi.x) * tanh_(gg.x);
        float cn1 = sigm(gf.y) * c.y + sigm(gi.y) * tanh_(gg.y);
        cst[p] = make_float2(cn0, cn1);
        hp[p] = make_float2(sigm(go.x) * tanh_(cn0), sigm(go.y) * tanh_(cn1));
    }
}

__global__ void __launch_bounds__(NT, 2)
lstm_traj_kernel(const float* __restrict__ x,
                 const float* __restrict__ eWih0, const float* __restrict__ eWhh0,
                 const float* __restrict__ ebih0, const float* __restrict__ ebhh0,
                 const float* __restrict__ eWih1, const float* __restrict__ eWhh1,
                 const float* __restrict__ ebih1, const float* __restrict__ ebhh1,
                 const float* __restrict__ dWih0, const float* __restrict__ dWhh0,
                 const float* __restrict__ dbih0, const float* __restrict__ dbhh0,
                 const float* __restrict__ dWih1, const float* __restrict__ dWhh1,
                 const float* __restrict__ dbih1, const float* __restrict__ dbhh1,
                 const float* __restrict__ fcW,  const float* __restrict__ fcb,
                 float* __restrict__ out)
{
    extern __shared__ float sm[];
    uint32_t smem_u32 = (uint32_t)__cvta_generic_to_shared(sm);
    const int tid = threadIdx.x;
    const int j  = tid >> 2;            // hidden unit 0..127
    const int rb = tid & 3;             // row block: rows rb*8..rb*8+7
    const int gr0 = blockIdx.x * BR;

    // zero h states
    for (int i = tid; i < 2 * 4608; i += NT) sm[i] = 0.0f;
    // combined biases (4 sets x 512)
    sm[OFF_BIAS + tid]        = ebih0[tid] + ebhh0[tid];
    sm[OFF_BIAS + 512 + tid]  = ebih1[tid] + ebhh1[tid];
    sm[OFF_BIAS + 1024 + tid] = dbih0[tid] + dbhh0[tid];
    sm[OFF_BIAS + 1536 + tid] = dbih1[tid] + dbhh1[tid];
    // FC weights, decoder ih0 (native [512][2])
    if (tid < 256) sm[OFF_FC + tid] = fcW[tid];
    if (tid < 2)   sm[OFF_FCB + tid] = fcb[tid];
    {
        float2 w = ((const float2*)dWih0)[tid];
        sm[OFF_DW + tid * 2]     = w.x;
        sm[OFF_DW + tid * 2 + 1] = w.y;
    }
    __syncthreads();

    // c-state in registers (thread-private)
    float2 c0st[4] = {{0,0},{0,0},{0,0},{0,0}};
    float2 c1st[4] = {{0,0},{0,0},{0,0},{0,0}};

    const float* hb0 = sm + OFF_H0 + rb * 8;
    const float* hb1 = sm + OFF_H1 + rb * 8;
    const float* xb  = sm + OFF_XS + rb * 8;

    // ======================= ENCODER =======================
#pragma unroll 1
    for (int t = 0; t < TT; t++) {
        {   // stage x_t transposed: xs[k][row], one element per thread
            int r = tid >> 4, k = tid & 15;
            sm[OFF_XS + k * HPAD + r] = x[(size_t)(gr0 + r) * (TT * 16) + t * 16 + k];
        }
        __syncthreads();

        u64 acc[4][4];
        // layer 0
        init_acc(acc, sm + OFF_BIAS, j);
        gemm_cp<2>(acc, eWih0, 16, xb, sm, smem_u32, tid, j);
        gemm_cp<16>(acc, eWhh0, 128, hb0, sm, smem_u32, tid, j);
        epilogue(acc, c0st, sm + OFF_H0, j, rb);
        __syncthreads();
        // layer 1
        init_acc(acc, sm + OFF_BIAS + 512, j);
        gemm_cp<16>(acc, eWih1, 128, hb0, sm, smem_u32, tid, j);
        gemm_cp<16>(acc, eWhh1, 128, hb1, sm, smem_u32, tid, j);
        epilogue(acc, c1st, sm + OFF_H1, j, rb);
        __syncthreads();
    }

    // ======================= DECODER setup =======================
    if (tid < BR) {   // dec_in = x[:, 99, :2]
        size_t base = (size_t)(gr0 + tid) * (TT * 16) + 99 * 16;
        sm[OFF_XS + tid]        = x[base + 0];
        sm[OFF_XS + HPAD + tid] = x[base + 1];
    }
    __syncthreads();

    // ======================= DECODER =======================
#pragma unroll 1
    for (int t = 0; t < TGTN; t++) {
        u64 acc[4][4];
        // layer 0: K=2 input (resident) + K=128 recurrent (streamed)
        init_acc(acc, sm + OFF_BIAS + 1024, j);
#pragma unroll
        for (int k = 0; k < 2; k++) {
            const float* w = sm + OFF_DW + j * 2 + k;
            u64 b0 = pk2(w[0]);
            u64 b1 = pk2(w[256]);
            u64 b2 = pk2(w[512]);
            u64 b3 = pk2(w[768]);
            const ulonglong2* hp = (const ulonglong2*)(xb + k * HPAD);
            ulonglong2 q0 = hp[0], q1 = hp[1];
            u64 a[4] = {q0.x, q0.y, q1.x, q1.y};
#pragma unroll
            for (int p = 0; p < 4; p++) {
                acc[0][p] = f2fma(a[p], b0, acc[0][p]);
                acc[1][p] = f2fma(a[p], b1, acc[1][p]);
                acc[2][p] = f2fma(a[p], b2, acc[2][p]);
                acc[3][p] = f2fma(a[p], b3, acc[3][p]);
            }
        }
        gemm_cp<16>(acc, dWhh0, 128, hb0, sm, smem_u32, tid, j);
        epilogue(acc, c0st, sm + OFF_H0, j, rb);
        __syncthreads();
        // layer 1
        init_acc(acc, sm + OFF_BIAS + 1536, j);
        gemm_cp<16>(acc, dWih1, 128, hb0, sm, smem_u32, tid, j);
        gemm_cp<16>(acc, dWhh1, 128, hb1, sm, smem_u32, tid, j);
        epilogue(acc, c1st, sm + OFF_H1, j, rb);
        __syncthreads();

        // FC + output + feedback
        if (tid < 2 * BR) {
            int r = tid >> 1;
            int o = tid & 1;
            float s = sm[OFF_FCB + o];
            const float* fw = sm + OFF_FC + o * 128;
            const float* hv = sm + OFF_H1 + r;
#pragma unroll 8
            for (int jj = 0; jj < 128; jj++) s += hv[jj * HPAD] * fw[jj];
            out[((size_t)(gr0 + r) * TGTN + t) * 2 + o] = s;
            sm[OFF_XS + o * HPAD + r] = s;
        }
        __syncthreads();
    }
}

extern "C" void kernel_launch(void* const* d_in, const int* in_sizes, int n_in,
                              void* d_out, int out_size)
{
    const float* x     = (const float*)d_in[0];
    const float* eWih0 = (const float*)d_in[2];
    const float* eWhh0 = (const float*)d_in[3];
    const float* ebih0 = (const float*)d_in[4];
    const float* ebhh0 = (const float*)d_in[5];
    const float* eWih1 = (const float*)d_in[6];
    const float* eWhh1 = (const float*)d_in[7];
    const float* ebih1 = (const float*)d_in[8];
    const float* ebhh1 = (const float*)d_in[9];
    const float* dWih0 = (const float*)d_in[10];
    const float* dWhh0 = (const float*)d_in[11];
    const float* dbih0 = (const float*)d_in[12];
    const float* dbhh0 = (const float*)d_in[13];
    const float* dWih1 = (const float*)d_in[14];
    const float* dWhh1 = (const float*)d_in[15];
    const float* dbih1 = (const float*)d_in[16];
    const float* dbhh1 = (const float*)d_in[17];
    const float* fcW   = (const float*)d_in[18];
    const float* fcb   = (const float*)d_in[19];
    float* out = (float*)d_out;

    cudaFuncSetAttribute(lstm_traj_kernel,
                         cudaFuncAttributeMaxDynamicSharedMemorySize, SMEM_BYTES);

    lstm_traj_kernel<<<BB / BR, NT, SMEM_BYTES>>>(
        x, eWih0, eWhh0, ebih0, ebhh0, eWih1, eWhh1, ebih1, ebhh1,
        dWih0, dWhh0, dbih0, dbhh0, dWih1, dWhh1, dbih1, dbhh1,
        fcW, fcb, out);
}

// round 8
// speedup vs baseline: 1.7426x; 1.7426x over previous
#include <cuda_runtime.h>
#include <cstdint>

// Problem constants
#define BB    8192
#define TT    100
#define TGTN  60

#define NT    256     // threads per CTA (8 warps)
#define BR    32      // batch rows per CTA
#define HPAD  36      // h row stride (floats)
#define CPAD  32      // c row stride (floats)
#define XPAD  32      // x/feedback row stride (floats)
#define CHUNKF 4096   // one weight buffer: [512 rows][8 k] floats (16KB)

// Shared layout (float offsets, all 16B-aligned)
#define OFF_H0   0                 // [128][36]
#define OFF_H1   4608              // [128][36]
#define OFF_C0   9216              // [128][32]
#define OFF_C1   13312             // [128][32]
#define OFF_WBUF 17408             // 2 x [512][8]
#define OFF_XS   25600             // [16][32]
#define OFF_FC   26112             // fcW [2][128]
#define OFF_FCB  26368             // fcb [2] + pad
#define OFF_DW   26372             // dWih0 native [512][2]
#define SMEM_FLOATS 27396
#define SMEM_BYTES  (SMEM_FLOATS*4)   // 109,584 B -> 2 CTAs/SM

typedef unsigned long long u64;

// ---- packed f32x2 helpers ----
__device__ __forceinline__ u64 pk2(float x) {
    u64 r; asm("mov.b64 %0, {%1, %1};" : "=l"(r) : "f"(x)); return r;
}
__device__ __forceinline__ u64 f2fma(u64 a, u64 b, u64 c) {
    u64 d; asm("fma.rn.f32x2 %0, %1, %2, %3;" : "=l"(d) : "l"(a), "l"(b), "l"(c)); return d;
}
__device__ __forceinline__ float2 up2(u64 v) {
    float2 f; asm("mov.b64 {%0, %1}, %2;" : "=f"(f.x), "=f"(f.y) : "l"(v)); return f;
}

// ---- activations ----
__device__ __forceinline__ float sigm(float x) {
    return __fdividef(1.0f, 1.0f + __expf(-x));
}
__device__ __forceinline__ float tanh_(float x) {
    float a = fabsf(x);
    float e = __expf(-2.0f * a);
    float t = __fdividef(1.0f - e, 1.0f + e);
    return copysignf(t, x);
}

__device__ __forceinline__ void init_acc(u64 acc[4][8], const float b[4])
{
#pragma unroll
    for (int g = 0; g < 4; g++) {
        u64 bb = pk2(b[g]);
#pragma unroll
        for (int p = 0; p < 8; p++) acc[g][p] = bb;
    }
}

// ---- streamed GEMM over K = NCH*8.
//      Weights: W [512][ldw] row-major global -> cp.async(8B) into [512][8]
//      buffers with XOR swizzle: word(r,k) = r*8 + (k ^ (2*((r>>2)&3))).
//      Activations: hb (= base + rb*16 floats), stride STRIDE per k.
//      Double buffer, one barrier per chunk, depth-1 prefetch. ----
template<int NCH, int STRIDE>
__device__ __forceinline__ void gemm_cp(u64 acc[4][8],
                                        const float* __restrict__ W, int ldw,
                                        const float* __restrict__ hb,
                                        const float* __restrict__ sm,
                                        uint32_t smem_u32, int tid, int j)
{
    const int r0 = tid * 2;
    const int kx = ((j >> 2) & 3) << 1;   // k-xor for this thread's gate rows

    auto issue = [&](int c) {
        int buf = c & 1;
#pragma unroll
        for (int rr = 0; rr < 2; rr++) {
            int r = r0 + rr;
            int s = (r >> 2) & 3;
            uint32_t dbase = smem_u32 + (uint32_t)((OFF_WBUF + buf * CHUNKF + r * 8) * 4);
            const float* src = W + (size_t)r * ldw + c * 8;
#pragma unroll
            for (int q = 0; q < 4; q++) {
                uint32_t dst = dbase + (uint32_t)(((q ^ s) << 3));
                asm volatile("cp.async.ca.shared.global [%0], [%1], 8;"
                             :: "r"(dst), "l"(src + q * 2));
            }
        }
        asm volatile("cp.async.commit_group;" ::: "memory");
    };

    issue(0);
#pragma unroll 1
    for (int c = 0; c < NCH; c++) {
        asm volatile("cp.async.wait_group 0;" ::: "memory");
        __syncthreads();                 // chunk c visible; other buffer's readers done
        if (c + 1 < NCH) issue(c + 1);
        const float* wb = sm + OFF_WBUF + (c & 1) * CHUNKF;
        const float* hc = hb + c * 8 * STRIDE;
#pragma unroll
        for (int k = 0; k < 8; k++) {
            int kk = k ^ kx;
            u64 b0 = pk2(wb[(j      ) * 8 + kk]);
            u64 b1 = pk2(wb[(j + 128) * 8 + kk]);
            u64 b2 = pk2(wb[(j + 256) * 8 + kk]);
            u64 b3 = pk2(wb[(j + 384) * 8 + kk]);
            const ulonglong2* hp = (const ulonglong2*)(hc + k * STRIDE);
            ulonglong2 q0 = hp[0], q1 = hp[1], q2 = hp[2], q3 = hp[3];
            u64 a[8] = {q0.x, q0.y, q1.x, q1.y, q2.x, q2.y, q3.x, q3.y};
#pragma unroll
            for (int p = 0; p < 8; p++) {
                acc[0][p] = f2fma(a[p], b0, acc[0][p]);
                acc[1][p] = f2fma(a[p], b1, acc[1][p]);
                acc[2][p] = f2fma(a[p], b2, acc[2][p]);
                acc[3][p] = f2fma(a[p], b3, acc[3][p]);
            }
        }
    }
    __syncthreads();   // protect h/x rewrites after this gemm from stragglers
}

// ---- LSTM pointwise epilogue: unit j, rows rb*16..rb*16+15; c in smem ----
__device__ __forceinline__ void epilogue(u64 acc[4][8],
                                         float* __restrict__ cs,
                                         float* __restrict__ hs,
                                         int j, int rb)
{
    float2* cp = (float2*)(cs + j * CPAD + rb * 16);
    float2* hp = (float2*)(hs + j * HPAD + rb * 16);
#pragma unroll
    for (int p = 0; p < 8; p++) {
        float2 gi = up2(acc[0][p]);
        float2 gf = up2(acc[1][p]);
        float2 gg = up2(acc[2][p]);
        float2 go = up2(acc[3][p]);
        float2 c = cp[p];
        float cn0 = sigm(gf.x) * c.x + sigm(gi.x) * tanh_(gg.x);
        float cn1 = sigm(gf.y) * c.y + sigm(gi.y) * tanh_(gg.y);
        cp[p] = make_float2(cn0, cn1);
        hp[p] = make_float2(sigm(go.x) * tanh_(cn0), sigm(go.y) * tanh_(cn1));
    }
}

__global__ void __launch_bounds__(NT, 2)
lstm_traj_kernel(const float* __restrict__ x,
                 const float* __restrict__ eWih0, const float* __restrict__ eWhh0,
                 const float* __restrict__ ebih0, const float* __restrict__ ebhh0,
                 const float* __restrict__ eWih1, const float* __restrict__ eWhh1,
                 const float* __restrict__ ebih1, const float* __restrict__ ebhh1,
                 const float* __restrict__ dWih0, const float* __restrict__ dWhh0,
                 const float* __restrict__ dbih0, const float* __restrict__ dbhh0,
                 const float* __restrict__ dWih1, const float* __restrict__ dWhh1,
                 const float* __restrict__ dbih1, const float* __restrict__ dbhh1,
                 const float* __restrict__ fcW,  const float* __restrict__ fcb,
                 float* __restrict__ out)
{
    extern __shared__ float sm[];
    uint32_t smem_u32 = (uint32_t)__cvta_generic_to_shared(sm);
    const int tid = threadIdx.x;
    const int j  = tid >> 1;            // hidden unit 0..127
    const int rb = tid & 1;             // row block: rows rb*16..rb*16+15
    const int gr0 = blockIdx.x * BR;

    // biases, combined, in registers
    float be0[4], be1[4], bd0[4], bd1[4];
#pragma unroll
    for (int g = 0; g < 4; g++) {
        int idx = g * 128 + j;
        be0[g] = ebih0[idx] + ebhh0[idx];
        be1[g] = ebih1[idx] + ebhh1[idx];
        bd0[g] = dbih0[idx] + dbhh0[idx];
        bd1[g] = dbih1[idx] + dbhh1[idx];
    }

    // zero h & c states; stage FC weights + dWih0 (once)
    for (int i = tid; i < OFF_WBUF; i += NT) sm[i] = 0.0f;
    sm[OFF_FC + tid] = fcW[tid];
    if (tid < 2) sm[OFF_FCB + tid] = fcb[tid];
    for (int i = tid; i < 1024; i += NT) sm[OFF_DW + i] = dWih0[i];
    __syncthreads();

    const float* hb0 = sm + OFF_H0 + rb * 16;
    const float* hb1 = sm + OFF_H1 + rb * 16;
    const float* xb  = sm + OFF_XS + rb * 16;

    // ======================= ENCODER =======================
#pragma unroll 1
    for (int t = 0; t < TT; t++) {
        // stage x_t transposed: xs[k][row]; 2 elems/thread; readers long gone
#pragma unroll
        for (int e = tid; e < 512; e += NT) {
            int r = e >> 4, k = e & 15;
            sm[OFF_XS + k * XPAD + r] = x[(size_t)(gr0 + r) * (TT * 16) + t * 16 + k];
        }
        // (no barrier: ih0's first-chunk barrier covers visibility)

        u64 acc[4][8];
        // layer 0
        init_acc(acc, be0);
        gemm_cp<2, XPAD>(acc, eWih0, 16, xb, sm, smem_u32, tid, j);
        gemm_cp<16, HPAD>(acc, eWhh0, 128, hb0, sm, smem_u32, tid, j);
        epilogue(acc, sm + OFF_C0, sm + OFF_H0, j, rb);
        // layer 1 (its first-chunk barrier orders epilogue0's h writes)
        init_acc(acc, be1);
        gemm_cp<16, HPAD>(acc, eWih1, 128, hb0, sm, smem_u32, tid, j);
        gemm_cp<16, HPAD>(acc, eWhh1, 128, hb1, sm, smem_u32, tid, j);
        epilogue(acc, sm + OFF_C1, sm + OFF_H1, j, rb);
        __syncthreads();   // h1 writes visible before next step's hh1 / FC
    }

    // ======================= DECODER setup =======================
    if (tid < BR) {   // dec_in = x[:, 99, :2]
        size_t base = (size_t)(gr0 + tid) * (TT * 16) + 99 * 16;
        sm[OFF_XS + tid]        = x[base + 0];
        sm[OFF_XS + XPAD + tid] = x[base + 1];
    }
    __syncthreads();

    // ======================= DECODER =======================
#pragma unroll 1
    for (int t = 0; t < TGTN; t++) {
        u64 acc[4][8];
        // layer 0: K=2 input from resident dW [512][2] + K=128 recurrent
        init_acc(acc, bd0);
#pragma unroll
        for (int k = 0; k < 2; k++) {
            const float* dw = sm + OFF_DW;
            u64 b0 = pk2(dw[(j      ) * 2 + k]);
            u64 b1 = pk2(dw[(j + 128) * 2 + k]);
            u64 b2 = pk2(dw[(j + 256) * 2 + k]);
            u64 b3 = pk2(dw[(j + 384) * 2 + k]);
            const ulonglong2* hp = (const ulonglong2*)(xb + k * XPAD);
            ulonglong2 q0 = hp[0], q1 = hp[1], q2 = hp[2], q3 = hp[3];
            u64 a[8] = {q0.x, q0.y, q1.x, q1.y, q2.x, q2.y, q3.x, q3.y};
#pragma unroll
            for (int p = 0; p < 8; p++) {
                acc[0][p] = f2fma(a[p], b0, acc[0][p]);
                acc[1][p] = f2fma(a[p], b1, acc[1][p]);
                acc[2][p] = f2fma(a[p], b2, acc[2][p]);
                acc[3][p] = f2fma(a[p], b3, acc[3][p]);
            }
        }
        gemm_cp<16, HPAD>(acc, dWhh0, 128, hb0, sm, smem_u32, tid, j);
        epilogue(acc, sm + OFF_C0, sm + OFF_H0, j, rb);
        // layer 1
        init_acc(acc, bd1);
        gemm_cp<16, HPAD>(acc, dWih1, 128, hb0, sm, smem_u32, tid, j);
        gemm_cp<16, HPAD>(acc, dWhh1, 128, hb1, sm, smem_u32, tid, j);
        epilogue(acc, sm + OFF_C1, sm + OFF_H1, j, rb);
        __syncthreads();   // h1 ready for FC

        // FC + output + feedback
        if (tid < 2 * BR) {
            int r = tid >> 1;
            int o = tid & 1;
            float s = sm[OFF_FCB + o];
            const float* fw = sm + OFF_FC + o * 128;
            const float* hv = sm + OFF_H1 + r;
#pragma unroll 8
            for (int jj = 0; jj < 128; jj++) s += hv[jj * HPAD] * fw[jj];
            out[((size_t)(gr0 + r) * TGTN + t) * 2 + o] = s;
            sm[OFF_XS + o * XPAD + r] = s;
        }
        __syncthreads();   // feedback visible before next step's K=2 accum
    }
}

extern "C" void kernel_launch(void* const* d_in, const int* in_sizes, int n_in,
                              void* d_out, int out_size)
{
    const float* x     = (const float*)d_in[0];
    const float* eWih0 = (const float*)d_in[2];
    const float* eWhh0 = (const float*)d_in[3];
    const float* ebih0 = (const float*)d_in[4];
    const float* ebhh0 = (const float*)d_in[5];
    const float* eWih1 = (const float*)d_in[6];
    const float* eWhh1 = (const float*)d_in[7];
    const float* ebih1 = (const float*)d_in[8];
    const float* ebhh1 = (const float*)d_in[9];
    const float* dWih0 = (const float*)d_in[10];
    const float* dWhh0 = (const float*)d_in[11];
    const float* dbih0 = (const float*)d_in[12];
    const float* dbhh0 = (const float*)d_in[13];
    const float* dWih1 = (const float*)d_in[14];
    const float* dWhh1 = (const float*)d_in[15];
    const float* dbih1 = (const float*)d_in[16];
    const float* dbhh1 = (const float*)d_in[17];
    const float* fcW   = (const float*)d_in[18];
    const float* fcb   = (const float*)d_in[19];
    float* out = (float*)d_out;

    cudaFuncSetAttribute(lstm_traj_kernel,
                         cudaFuncAttributeMaxDynamicSharedMemorySize, SMEM_BYTES);

    lstm_traj_kernel<<<BB / BR, NT, SMEM_BYTES>>>(
        x, eWih0, eWhh0, ebih0, ebhh0, eWih1, eWhh1, ebih1, ebhh1,
        dWih0, dWhh0, dbih0, dbhh0, dWih1, dWhh1, dbih1, dbhh1,
        fcW, fcb, out);
}